// round 1
// baseline (speedup 1.0000x reference)
#include <cuda_runtime.h>

// out[i] = sum_j S[i][j] * w[j],  N = 16384.
// HBM-bound: 1.074 GB of S traffic. One CTA per row, float4 coalesced loads,
// 16 independent LDG.128 per thread for high MLP, two-level reduction.

#define N_DIM 16384
#define THREADS 256

__global__ __launch_bounds__(THREADS, 8)
void matvec_rowsum_kernel(const float* __restrict__ S,
                          const float* __restrict__ w,
                          float* __restrict__ out)
{
    const int row = blockIdx.x;
    const int tid = threadIdx.x;

    const float4* Srow = reinterpret_cast<const float4*>(S + (size_t)row * N_DIM);
    const float4* W4   = reinterpret_cast<const float4*>(w);

    // N_DIM/4 = 4096 float4 per row; 256 threads -> 16 float4 per thread.
    float acc = 0.0f;
    #pragma unroll
    for (int it = 0; it < 16; ++it) {
        const int idx = tid + it * THREADS;     // coalesced across warp
        float4 s = __ldg(&Srow[idx]);
        float4 wv = __ldg(&W4[idx]);
        acc = fmaf(s.x, wv.x, acc);
        acc = fmaf(s.y, wv.y, acc);
        acc = fmaf(s.z, wv.z, acc);
        acc = fmaf(s.w, wv.w, acc);
    }

    // Warp reduction
    #pragma unroll
    for (int off = 16; off > 0; off >>= 1)
        acc += __shfl_xor_sync(0xFFFFFFFFu, acc, off);

    // Cross-warp reduction via smem
    __shared__ float warp_sums[THREADS / 32];
    const int lane = tid & 31;
    const int wid  = tid >> 5;
    if (lane == 0) warp_sums[wid] = acc;
    __syncthreads();

    if (wid == 0) {
        float v = (lane < THREADS / 32) ? warp_sums[lane] : 0.0f;
        #pragma unroll
        for (int off = 4; off > 0; off >>= 1)
            v += __shfl_xor_sync(0xFFFFFFFFu, v, off);
        if (lane == 0) out[row] = v;
    }
}

extern "C" void kernel_launch(void* const* d_in, const int* in_sizes, int n_in,
                              void* d_out, int out_size)
{
    const float* S = (const float*)d_in[0];
    const float* w = (const float*)d_in[1];
    float* out = (float*)d_out;

    matvec_rowsum_kernel<<<N_DIM, THREADS>>>(S, w, out);
}